// round 1
// baseline (speedup 1.0000x reference)
#include <cuda_runtime.h>
#include <math.h>

#define SEQ   4096
#define EMBED 1280
#define HEADS 16
#define HDIM  80
#define QKV_N (3 * EMBED)

// Scratch (static device globals: allocation-guard safe)
__device__ float g_qkv[(size_t)SEQ * QKV_N];   // 4096 x 3840
__device__ float g_attn[(size_t)SEQ * EMBED];  // 4096 x 1280

// ---------------------------------------------------------------------------
// Classic register-blocked SGEMM + bias: C[M,N] = A[M,K] @ B[K,N] + bias[N]
// BM=BN=128, BK=8, TM=TN=8, 256 threads. M%128==0, N%128==0, K%8==0 assumed.
// ---------------------------------------------------------------------------
__global__ __launch_bounds__(256) void sgemm_bias_kernel(
    const float* __restrict__ A, const float* __restrict__ B,
    const float* __restrict__ bias, float* __restrict__ C,
    int M, int N, int K)
{
    __shared__ float As[8][128];
    __shared__ float Bs[8][128];

    const int tid  = threadIdx.x;
    const int tr   = tid >> 4;          // 0..15 (row group)
    const int tc   = tid & 15;          // 0..15 (col group)
    const int brow = blockIdx.y * 128;
    const int bcol = blockIdx.x * 128;

    const int arow = tid >> 1;               // 0..127
    const int acol = (tid & 1) << 2;         // 0 or 4
    const int blr  = tid >> 5;               // 0..7
    const int blc  = (tid & 31) << 2;        // 0..124

    const float* Aptr = A + (size_t)(brow + arow) * K + acol;
    const float* Bptr = B + (size_t)blr * N + bcol + blc;

    float acc[8][8];
#pragma unroll
    for (int i = 0; i < 8; i++)
#pragma unroll
        for (int j = 0; j < 8; j++) acc[i][j] = 0.f;

    for (int kt = 0; kt < K; kt += 8) {
        float4 av = *(const float4*)(Aptr + kt);
        As[acol + 0][arow] = av.x;
        As[acol + 1][arow] = av.y;
        As[acol + 2][arow] = av.z;
        As[acol + 3][arow] = av.w;
        float4 bv = *(const float4*)(Bptr + (size_t)kt * N);
        *(float4*)&Bs[blr][blc] = bv;
        __syncthreads();

#pragma unroll
        for (int k = 0; k < 8; k++) {
            float4 a0 = *(const float4*)&As[k][tr * 8];
            float4 a1 = *(const float4*)&As[k][tr * 8 + 4];
            float4 b0 = *(const float4*)&Bs[k][tc * 8];
            float4 b1 = *(const float4*)&Bs[k][tc * 8 + 4];
            float rm[8] = {a0.x, a0.y, a0.z, a0.w, a1.x, a1.y, a1.z, a1.w};
            float rn[8] = {b0.x, b0.y, b0.z, b0.w, b1.x, b1.y, b1.z, b1.w};
#pragma unroll
            for (int i = 0; i < 8; i++)
#pragma unroll
                for (int j = 0; j < 8; j++)
                    acc[i][j] = fmaf(rm[i], rn[j], acc[i][j]);
        }
        __syncthreads();
    }

    const int cbase = bcol + tc * 8;
#pragma unroll
    for (int i = 0; i < 8; i++) {
        const int row = brow + tr * 8 + i;
        float4 o0, o1;
        o0.x = acc[i][0] + bias[cbase + 0];
        o0.y = acc[i][1] + bias[cbase + 1];
        o0.z = acc[i][2] + bias[cbase + 2];
        o0.w = acc[i][3] + bias[cbase + 3];
        o1.x = acc[i][4] + bias[cbase + 4];
        o1.y = acc[i][5] + bias[cbase + 5];
        o1.z = acc[i][6] + bias[cbase + 6];
        o1.w = acc[i][7] + bias[cbase + 7];
        *(float4*)(C + (size_t)row * N + cbase)     = o0;
        *(float4*)(C + (size_t)row * N + cbase + 4) = o1;
    }
}

// ---------------------------------------------------------------------------
// Interleaved RoPE applied in-place to the Q and K slices of g_qkv.
// q'[2i]   = q[2i]*cos[2i]   - q[2i+1]*sin[2i]
// q'[2i+1] = q[2i+1]*cos[2i+1] + q[2i]*sin[2i+1]
// ---------------------------------------------------------------------------
__global__ __launch_bounds__(256) void rope_kernel(
    const float* __restrict__ cs, const float* __restrict__ sn,
    float* __restrict__ qkv)
{
    int idx = blockIdx.x * blockDim.x + threadIdx.x;       // one pair each
    const int total = SEQ * 2 * HEADS * (HDIM / 2);        // 4096*1280 pairs
    if (idx >= total) return;
    int s     = idx / 1280;
    int rem   = idx - s * 1280;
    int which = rem / 640;          // 0 = q, 1 = k
    int p     = rem - which * 640;
    int h     = p / 40;
    int i     = p - h * 40;
    int col   = which * EMBED + h * HDIM + 2 * i;

    float* base = qkv + (size_t)s * QKV_N + col;
    float x0 = base[0];
    float x1 = base[1];
    float c0 = cs[s * HDIM + 2 * i];
    float c1 = cs[s * HDIM + 2 * i + 1];
    float s0 = sn[s * HDIM + 2 * i];
    float s1 = sn[s * HDIM + 2 * i + 1];
    base[0] = x0 * c0 - x1 * s0;
    base[1] = x1 * c1 + x0 * s1;
}

// ---------------------------------------------------------------------------
// Flash attention (fp32, non-causal). One block = (head, 64-row Q tile).
// 256 threads as 16x16: thread (ty,tx) owns S[4ty..+3][4tx..+3] during QK^T
// and O[4ty..+3][5tx..+4] during PV. Online softmax with shfl row-reductions
// across the 16-lane half-warp row groups.
// ---------------------------------------------------------------------------
#define QS_STRIDE 81
#define PS_STRIDE 65
#define FLASH_SMEM_FLOATS (64*QS_STRIDE + 64*QS_STRIDE + 64*HDIM + 64*PS_STRIDE)
#define FLASH_SMEM_BYTES  (FLASH_SMEM_FLOATS * 4)

__global__ __launch_bounds__(256) void flash_kernel(
    const float* __restrict__ qkv, float* __restrict__ out)
{
    extern __shared__ float smf[];
    float* Qs = smf;                    // [64][81]
    float* Ks = Qs + 64 * QS_STRIDE;    // [64][81]
    float* Vs = Ks + 64 * QS_STRIDE;    // [64][80]
    float* Ps = Vs + 64 * HDIM;         // [64][65]

    const int h    = blockIdx.y;
    const int q0   = blockIdx.x << 6;
    const int tid  = threadIdx.x;
    const int ty   = tid >> 4;
    const int tx   = tid & 15;
    const int qcol = h * HDIM;
    const float scaling = 0.11180339887498948f;  // 80^-0.5

    // Load Q tile, pre-scaled
    for (int i = tid; i < 64 * 20; i += 256) {
        int r = i / 20;
        int d = (i % 20) << 2;
        float4 v = *(const float4*)(qkv + (size_t)(q0 + r) * QKV_N + qcol + d);
        float* q = Qs + r * QS_STRIDE + d;
        q[0] = v.x * scaling; q[1] = v.y * scaling;
        q[2] = v.z * scaling; q[3] = v.w * scaling;
    }

    float o[4][5];
#pragma unroll
    for (int i = 0; i < 4; i++)
#pragma unroll
        for (int dd = 0; dd < 5; dd++) o[i][dd] = 0.f;
    float m_i[4], l_i[4];
#pragma unroll
    for (int i = 0; i < 4; i++) { m_i[i] = -INFINITY; l_i[i] = 0.f; }

    for (int kb = 0; kb < 64; kb++) {
        __syncthreads();   // previous tile's smem readers done
        const int k0 = kb << 6;
        for (int i = tid; i < 64 * 20; i += 256) {
            int r = i / 20;
            int d = (i % 20) << 2;
            const float* src = qkv + (size_t)(k0 + r) * QKV_N + qcol + d;
            float4 kv = *(const float4*)(src + EMBED);
            float* kd = Ks + r * QS_STRIDE + d;
            kd[0] = kv.x; kd[1] = kv.y; kd[2] = kv.z; kd[3] = kv.w;
            float4 vv = *(const float4*)(src + 2 * EMBED);
            *(float4*)(Vs + r * HDIM + d) = vv;
        }
        __syncthreads();

        // S = Q K^T (Q pre-scaled)
        float sacc[4][4];
#pragma unroll
        for (int i = 0; i < 4; i++)
#pragma unroll
            for (int j = 0; j < 4; j++) sacc[i][j] = 0.f;

#pragma unroll 4
        for (int d = 0; d < HDIM; d++) {
            float qr[4], kc[4];
#pragma unroll
            for (int i = 0; i < 4; i++) qr[i] = Qs[(4 * ty + i) * QS_STRIDE + d];
#pragma unroll
            for (int j = 0; j < 4; j++) kc[j] = Ks[(4 * tx + j) * QS_STRIDE + d];
#pragma unroll
            for (int i = 0; i < 4; i++)
#pragma unroll
                for (int j = 0; j < 4; j++)
                    sacc[i][j] = fmaf(qr[i], kc[j], sacc[i][j]);
        }

        // Online softmax update
#pragma unroll
        for (int i = 0; i < 4; i++) {
            float rm = fmaxf(fmaxf(sacc[i][0], sacc[i][1]),
                             fmaxf(sacc[i][2], sacc[i][3]));
            rm = fmaxf(rm, __shfl_xor_sync(0xffffffffu, rm, 1));
            rm = fmaxf(rm, __shfl_xor_sync(0xffffffffu, rm, 2));
            rm = fmaxf(rm, __shfl_xor_sync(0xffffffffu, rm, 4));
            rm = fmaxf(rm, __shfl_xor_sync(0xffffffffu, rm, 8));
            float mn    = fmaxf(m_i[i], rm);
            float alpha = __expf(m_i[i] - mn);    // first iter: exp(-inf)=0
            float rs = 0.f;
#pragma unroll
            for (int j = 0; j < 4; j++) {
                sacc[i][j] = __expf(sacc[i][j] - mn);
                rs += sacc[i][j];
            }
            rs += __shfl_xor_sync(0xffffffffu, rs, 1);
            rs += __shfl_xor_sync(0xffffffffu, rs, 2);
            rs += __shfl_xor_sync(0xffffffffu, rs, 4);
            rs += __shfl_xor_sync(0xffffffffu, rs, 8);
            l_i[i] = l_i[i] * alpha + rs;
            m_i[i] = mn;
#pragma unroll
            for (int dd = 0; dd < 5; dd++) o[i][dd] *= alpha;
        }

        // Stage P to smem, then O += P @ V
#pragma unroll
        for (int i = 0; i < 4; i++)
#pragma unroll
            for (int j = 0; j < 4; j++)
                Ps[(4 * ty + i) * PS_STRIDE + 4 * tx + j] = sacc[i][j];
        __syncthreads();

#pragma unroll 2
        for (int c = 0; c < 64; c++) {
            float pr[4], vv[5];
#pragma unroll
            for (int i = 0; i < 4; i++) pr[i] = Ps[(4 * ty + i) * PS_STRIDE + c];
#pragma unroll
            for (int dd = 0; dd < 5; dd++) vv[dd] = Vs[c * HDIM + 5 * tx + dd];
#pragma unroll
            for (int i = 0; i < 4; i++)
#pragma unroll
                for (int dd = 0; dd < 5; dd++)
                    o[i][dd] = fmaf(pr[i], vv[dd], o[i][dd]);
        }
    }

    // Normalize and write
#pragma unroll
    for (int i = 0; i < 4; i++) {
        float inv = 1.f / l_i[i];
        int row = q0 + 4 * ty + i;
#pragma unroll
        for (int dd = 0; dd < 5; dd++)
            out[(size_t)row * EMBED + qcol + 5 * tx + dd] = o[i][dd] * inv;
    }
}

// ---------------------------------------------------------------------------
extern "C" void kernel_launch(void* const* d_in, const int* in_sizes, int n_in,
                              void* d_out, int out_size)
{
    const float* hidden = (const float*)d_in[0];   // (4096,1280)
    const float* cosv   = (const float*)d_in[1];   // (4096,80)
    const float* sinv   = (const float*)d_in[2];   // (4096,80)
    const float* w_qkv  = (const float*)d_in[3];   // (1280,3840)
    const float* b_qkv  = (const float*)d_in[4];   // (3840,)
    const float* w_proj = (const float*)d_in[5];   // (1280,1280)
    const float* b_proj = (const float*)d_in[6];   // (1280,)
    float* outp = (float*)d_out;                   // (4096,1280)

    float *qkv_ptr = nullptr, *attn_ptr = nullptr;
    cudaGetSymbolAddress((void**)&qkv_ptr, g_qkv);
    cudaGetSymbolAddress((void**)&attn_ptr, g_attn);

    cudaFuncSetAttribute(flash_kernel,
                         cudaFuncAttributeMaxDynamicSharedMemorySize,
                         FLASH_SMEM_BYTES);

    // 1) QKV projection
    dim3 g1(QKV_N / 128, SEQ / 128);
    sgemm_bias_kernel<<<g1, 256>>>(hidden, w_qkv, b_qkv, qkv_ptr,
                                   SEQ, QKV_N, EMBED);
    // 2) RoPE on Q,K
    int rope_total = SEQ * 1280;
    rope_kernel<<<(rope_total + 255) / 256, 256>>>(cosv, sinv, qkv_ptr);
    // 3) Flash attention
    flash_kernel<<<dim3(SEQ / 64, HEADS), 256, FLASH_SMEM_BYTES>>>(qkv_ptr,
                                                                   attn_ptr);
    // 4) Output projection
    dim3 g2(EMBED / 128, SEQ / 128);
    sgemm_bias_kernel<<<g2, 256>>>(attn_ptr, w_proj, b_proj, outp,
                                   SEQ, EMBED, EMBED);
}

// round 2
// speedup vs baseline: 3.4609x; 3.4609x over previous
#include <cuda_runtime.h>
#include <math.h>
#include <stdint.h>

#define SEQ   4096
#define EMBED 1280
#define HEADS 16
#define HDIM  80
#define QKV_N (3 * EMBED)

// Scratch (static device globals: allocation-guard safe)
__device__ float g_qkv[(size_t)SEQ * QKV_N];   // 4096 x 3840
__device__ float g_attn[(size_t)SEQ * EMBED];  // 4096 x 1280

// ---------------------------------------------------------------------------
// tf32 helpers
// ---------------------------------------------------------------------------
__device__ __forceinline__ uint32_t f2tf32(float x) {
    uint32_t r;
    asm("cvt.rna.tf32.f32 %0, %1;" : "=r"(r) : "f"(x));
    return r;
}

__device__ __forceinline__ void mma_tf32(
    float& c0, float& c1, float& c2, float& c3,
    uint32_t a0, uint32_t a1, uint32_t a2, uint32_t a3,
    uint32_t b0, uint32_t b1)
{
    asm volatile(
        "mma.sync.aligned.m16n8k8.row.col.f32.tf32.tf32.f32 "
        "{%0,%1,%2,%3}, {%4,%5,%6,%7}, {%8,%9}, {%0,%1,%2,%3};"
        : "+f"(c0), "+f"(c1), "+f"(c2), "+f"(c3)
        : "r"(a0), "r"(a1), "r"(a2), "r"(a3), "r"(b0), "r"(b1));
}

// ---------------------------------------------------------------------------
// tf32 tensor-core GEMM + bias: C[M,N] = A[M,K] @ B[K,N] + bias[N]
// BM=BN=128, BK=16, 256 threads (8 warps, 4x2), warp tile 32x64.
// Double-buffered smem, conflict-free padded strides.
// ---------------------------------------------------------------------------
#define AS_STR 20
#define BS_STR 136

__global__ __launch_bounds__(256) void gemm_tf32_kernel(
    const float* __restrict__ A, const float* __restrict__ B,
    const float* __restrict__ bias, float* __restrict__ C,
    int M, int N, int K)
{
    __shared__ uint32_t As[2][128][AS_STR];
    __shared__ uint32_t Bs[2][16][BS_STR];

    const int tid  = threadIdx.x;
    const int wid  = tid >> 5;
    const int lane = tid & 31;
    const int g    = lane >> 2;
    const int t    = lane & 3;
    const int m0   = (wid & 3) * 32;
    const int n0   = (wid >> 2) * 64;
    const int brow = blockIdx.y * 128;
    const int bcol = blockIdx.x * 128;

    float acc[2][8][4];
#pragma unroll
    for (int mc = 0; mc < 2; mc++)
#pragma unroll
        for (int nc = 0; nc < 8; nc++)
#pragma unroll
            for (int j = 0; j < 4; j++) acc[mc][nc][j] = 0.f;

    // preload tile 0
#pragma unroll
    for (int i = 0; i < 2; i++) {
        int s = tid + i * 256;
        int r = s >> 2, c = (s & 3) << 2;
        float4 v = *(const float4*)(A + (size_t)(brow + r) * K + c);
        uint32_t* ap = &As[0][r][c];
        ap[0] = f2tf32(v.x); ap[1] = f2tf32(v.y);
        ap[2] = f2tf32(v.z); ap[3] = f2tf32(v.w);
        int rb = s >> 5, cb = (s & 31) << 2;
        float4 w = *(const float4*)(B + (size_t)rb * N + bcol + cb);
        uint32_t* bp = &Bs[0][rb][cb];
        bp[0] = f2tf32(w.x); bp[1] = f2tf32(w.y);
        bp[2] = f2tf32(w.z); bp[3] = f2tf32(w.w);
    }
    __syncthreads();

    const int nk = K / 16;
    int buf = 0;
    for (int kt = 0; kt < nk; kt++) {
        float4 vA[2], vB[2];
        const bool pf = (kt + 1 < nk);
        if (pf) {
#pragma unroll
            for (int i = 0; i < 2; i++) {
                int s = tid + i * 256;
                int r = s >> 2, c = (s & 3) << 2;
                vA[i] = *(const float4*)(A + (size_t)(brow + r) * K + (kt + 1) * 16 + c);
                int rb = s >> 5, cb = (s & 31) << 2;
                vB[i] = *(const float4*)(B + (size_t)((kt + 1) * 16 + rb) * N + bcol + cb);
            }
        }
#pragma unroll
        for (int kc = 0; kc < 2; kc++) {
            uint32_t af[2][4];
#pragma unroll
            for (int mc = 0; mc < 2; mc++) {
                int row = m0 + mc * 16;
                af[mc][0] = As[buf][row + g][kc * 8 + t];
                af[mc][1] = As[buf][row + g + 8][kc * 8 + t];
                af[mc][2] = As[buf][row + g][kc * 8 + t + 4];
                af[mc][3] = As[buf][row + g + 8][kc * 8 + t + 4];
            }
#pragma unroll
            for (int nc = 0; nc < 8; nc++) {
                uint32_t b0 = Bs[buf][kc * 8 + t][n0 + nc * 8 + g];
                uint32_t b1 = Bs[buf][kc * 8 + t + 4][n0 + nc * 8 + g];
#pragma unroll
                for (int mc = 0; mc < 2; mc++)
                    mma_tf32(acc[mc][nc][0], acc[mc][nc][1],
                             acc[mc][nc][2], acc[mc][nc][3],
                             af[mc][0], af[mc][1], af[mc][2], af[mc][3],
                             b0, b1);
            }
        }
        if (pf) {
#pragma unroll
            for (int i = 0; i < 2; i++) {
                int s = tid + i * 256;
                int r = s >> 2, c = (s & 3) << 2;
                uint32_t* ap = &As[buf ^ 1][r][c];
                ap[0] = f2tf32(vA[i].x); ap[1] = f2tf32(vA[i].y);
                ap[2] = f2tf32(vA[i].z); ap[3] = f2tf32(vA[i].w);
                int rb = s >> 5, cb = (s & 31) << 2;
                uint32_t* bp = &Bs[buf ^ 1][rb][cb];
                bp[0] = f2tf32(vB[i].x); bp[1] = f2tf32(vB[i].y);
                bp[2] = f2tf32(vB[i].z); bp[3] = f2tf32(vB[i].w);
            }
        }
        __syncthreads();
        buf ^= 1;
    }

    // epilogue: bias + store (float2 per fragment row)
#pragma unroll
    for (int mc = 0; mc < 2; mc++) {
        int row_lo = brow + m0 + mc * 16 + g;
#pragma unroll
        for (int nc = 0; nc < 8; nc++) {
            int col = bcol + n0 + nc * 8 + 2 * t;
            float b0v = bias[col], b1v = bias[col + 1];
            *(float2*)(C + (size_t)row_lo * N + col) =
                make_float2(acc[mc][nc][0] + b0v, acc[mc][nc][1] + b1v);
            *(float2*)(C + (size_t)(row_lo + 8) * N + col) =
                make_float2(acc[mc][nc][2] + b0v, acc[mc][nc][3] + b1v);
        }
    }
}

// ---------------------------------------------------------------------------
// Interleaved RoPE applied in-place to the Q and K slices of g_qkv.
// ---------------------------------------------------------------------------
__global__ __launch_bounds__(256) void rope_kernel(
    const float* __restrict__ cs, const float* __restrict__ sn,
    float* __restrict__ qkv)
{
    int idx = blockIdx.x * blockDim.x + threadIdx.x;
    const int total = SEQ * 1280;
    if (idx >= total) return;
    int s     = idx / 1280;
    int rem   = idx - s * 1280;
    int which = rem / 640;
    int p     = rem - which * 640;
    int h     = p / 40;
    int i     = p - h * 40;
    int col   = which * EMBED + h * HDIM + 2 * i;

    float* base = qkv + (size_t)s * QKV_N + col;
    float x0 = base[0];
    float x1 = base[1];
    float c0 = cs[s * HDIM + 2 * i];
    float c1 = cs[s * HDIM + 2 * i + 1];
    float s0 = sn[s * HDIM + 2 * i];
    float s1 = sn[s * HDIM + 2 * i + 1];
    base[0] = x0 * c0 - x1 * s0;
    base[1] = x1 * c1 + x0 * s1;
}

// ---------------------------------------------------------------------------
// Flash attention, tf32 mma. One block = (head, 64-row Q tile), 4 warps.
// Warp w owns Q rows [w*16, w*16+16). Q fragments register-resident.
// K/V/P staged in smem with conflict-free padded strides.
// ---------------------------------------------------------------------------
#define KS_STR 84
#define VS_STR 88
#define PS_STR 68
#define FLASH_SMEM_BYTES ((64 * KS_STR + 64 * VS_STR + 64 * PS_STR) * 4)

__global__ __launch_bounds__(128) void flash_tf32_kernel(
    const float* __restrict__ qkv, float* __restrict__ out)
{
    extern __shared__ uint32_t sm[];
    uint32_t* Ks = sm;                     // [64][84]
    uint32_t* Vs = Ks + 64 * KS_STR;       // [64][88]
    uint32_t* Ps = Vs + 64 * VS_STR;       // [64][68]

    const int h    = blockIdx.y;
    const int q0   = blockIdx.x << 6;
    const int tid  = threadIdx.x;
    const int wid  = tid >> 5;
    const int lane = tid & 31;
    const int g    = lane >> 2;
    const int t    = lane & 3;
    const int m0   = wid * 16;
    const int qcol = h * HDIM;
    const float scal = 0.11180339887498948f;  // 80^-0.5

    // Stage Q (pre-scaled, tf32) into Ks, then lift fragments to registers.
    for (int i = tid; i < 64 * 20; i += 128) {
        int r = i / 20, d = (i % 20) << 2;
        float4 v = *(const float4*)(qkv + (size_t)(q0 + r) * QKV_N + qcol + d);
        uint32_t* p = Ks + r * KS_STR + d;
        p[0] = f2tf32(v.x * scal); p[1] = f2tf32(v.y * scal);
        p[2] = f2tf32(v.z * scal); p[3] = f2tf32(v.w * scal);
    }
    __syncthreads();

    uint32_t qf[10][4];
#pragma unroll
    for (int kc = 0; kc < 10; kc++) {
        qf[kc][0] = Ks[(m0 + g) * KS_STR + kc * 8 + t];
        qf[kc][1] = Ks[(m0 + g + 8) * KS_STR + kc * 8 + t];
        qf[kc][2] = Ks[(m0 + g) * KS_STR + kc * 8 + t + 4];
        qf[kc][3] = Ks[(m0 + g + 8) * KS_STR + kc * 8 + t + 4];
    }

    float o[10][4];
#pragma unroll
    for (int nt = 0; nt < 10; nt++)
#pragma unroll
        for (int j = 0; j < 4; j++) o[nt][j] = 0.f;
    float m_lo = -INFINITY, m_hi = -INFINITY, l_lo = 0.f, l_hi = 0.f;

    for (int kb = 0; kb < 64; kb++) {
        __syncthreads();  // all readers of Ks/Vs/Ps from prior iter done
        const int k0 = kb << 6;
        for (int i = tid; i < 64 * 20; i += 128) {
            int r = i / 20, d = (i % 20) << 2;
            const float* src = qkv + (size_t)(k0 + r) * QKV_N + qcol + d;
            float4 kv = *(const float4*)(src + EMBED);
            uint32_t* kp = Ks + r * KS_STR + d;
            kp[0] = f2tf32(kv.x); kp[1] = f2tf32(kv.y);
            kp[2] = f2tf32(kv.z); kp[3] = f2tf32(kv.w);
            float4 vv = *(const float4*)(src + 2 * EMBED);
            uint32_t* vp = Vs + r * VS_STR + d;
            vp[0] = f2tf32(vv.x); vp[1] = f2tf32(vv.y);
            vp[2] = f2tf32(vv.z); vp[3] = f2tf32(vv.w);
        }
        __syncthreads();

        // S = Q @ K^T : 8 n-tiles of 16x8 per warp
        float s[8][4];
#pragma unroll
        for (int nc = 0; nc < 8; nc++)
#pragma unroll
            for (int j = 0; j < 4; j++) s[nc][j] = 0.f;

#pragma unroll
        for (int nc = 0; nc < 8; nc++) {
#pragma unroll
            for (int kc = 0; kc < 10; kc++) {
                uint32_t b0 = Ks[(nc * 8 + g) * KS_STR + kc * 8 + t];
                uint32_t b1 = Ks[(nc * 8 + g) * KS_STR + kc * 8 + t + 4];
                mma_tf32(s[nc][0], s[nc][1], s[nc][2], s[nc][3],
                         qf[kc][0], qf[kc][1], qf[kc][2], qf[kc][3], b0, b1);
            }
        }

        // Online softmax. Thread owns rows (m0+g): c0,c1 and (m0+g+8): c2,c3.
        float mx_lo = -INFINITY, mx_hi = -INFINITY;
#pragma unroll
        for (int nc = 0; nc < 8; nc++) {
            mx_lo = fmaxf(mx_lo, fmaxf(s[nc][0], s[nc][1]));
            mx_hi = fmaxf(mx_hi, fmaxf(s[nc][2], s[nc][3]));
        }
        mx_lo = fmaxf(mx_lo, __shfl_xor_sync(0xffffffffu, mx_lo, 1));
        mx_lo = fmaxf(mx_lo, __shfl_xor_sync(0xffffffffu, mx_lo, 2));
        mx_hi = fmaxf(mx_hi, __shfl_xor_sync(0xffffffffu, mx_hi, 1));
        mx_hi = fmaxf(mx_hi, __shfl_xor_sync(0xffffffffu, mx_hi, 2));
        float mn_lo = fmaxf(m_lo, mx_lo);
        float mn_hi = fmaxf(m_hi, mx_hi);
        float alpha_lo = __expf(m_lo - mn_lo);
        float alpha_hi = __expf(m_hi - mn_hi);
        float sum_lo = 0.f, sum_hi = 0.f;
#pragma unroll
        for (int nc = 0; nc < 8; nc++) {
            s[nc][0] = __expf(s[nc][0] - mn_lo);
            s[nc][1] = __expf(s[nc][1] - mn_lo);
            s[nc][2] = __expf(s[nc][2] - mn_hi);
            s[nc][3] = __expf(s[nc][3] - mn_hi);
            sum_lo += s[nc][0] + s[nc][1];
            sum_hi += s[nc][2] + s[nc][3];
        }
        sum_lo += __shfl_xor_sync(0xffffffffu, sum_lo, 1);
        sum_lo += __shfl_xor_sync(0xffffffffu, sum_lo, 2);
        sum_hi += __shfl_xor_sync(0xffffffffu, sum_hi, 1);
        sum_hi += __shfl_xor_sync(0xffffffffu, sum_hi, 2);
        l_lo = l_lo * alpha_lo + sum_lo;
        l_hi = l_hi * alpha_hi + sum_hi;
        m_lo = mn_lo;
        m_hi = mn_hi;
#pragma unroll
        for (int nt = 0; nt < 10; nt++) {
            o[nt][0] *= alpha_lo; o[nt][1] *= alpha_lo;
            o[nt][2] *= alpha_hi; o[nt][3] *= alpha_hi;
        }

        // Stage P (tf32) into Ps
#pragma unroll
        for (int nc = 0; nc < 8; nc++) {
            uint32_t* plo = Ps + (m0 + g) * PS_STR + nc * 8 + 2 * t;
            plo[0] = f2tf32(s[nc][0]);
            plo[1] = f2tf32(s[nc][1]);
            uint32_t* phi = Ps + (m0 + g + 8) * PS_STR + nc * 8 + 2 * t;
            phi[0] = f2tf32(s[nc][2]);
            phi[1] = f2tf32(s[nc][3]);
        }
        __syncthreads();

        // O += P @ V : K = 64 (8 chunks), N = 80 (10 tiles)
#pragma unroll
        for (int kc = 0; kc < 8; kc++) {
            uint32_t a0 = Ps[(m0 + g) * PS_STR + kc * 8 + t];
            uint32_t a1 = Ps[(m0 + g + 8) * PS_STR + kc * 8 + t];
            uint32_t a2 = Ps[(m0 + g) * PS_STR + kc * 8 + t + 4];
            uint32_t a3 = Ps[(m0 + g + 8) * PS_STR + kc * 8 + t + 4];
#pragma unroll
            for (int nt = 0; nt < 10; nt++) {
                uint32_t b0 = Vs[(kc * 8 + t) * VS_STR + nt * 8 + g];
                uint32_t b1 = Vs[(kc * 8 + t + 4) * VS_STR + nt * 8 + g];
                mma_tf32(o[nt][0], o[nt][1], o[nt][2], o[nt][3],
                         a0, a1, a2, a3, b0, b1);
            }
        }
    }

    // Normalize and write (float2 per fragment row)
    float inv_lo = 1.f / l_lo;
    float inv_hi = 1.f / l_hi;
    int row_lo = q0 + m0 + g;
    int row_hi = row_lo + 8;
#pragma unroll
    for (int nt = 0; nt < 10; nt++) {
        int col = qcol + nt * 8 + 2 * t;
        *(float2*)(out + (size_t)row_lo * EMBED + col) =
            make_float2(o[nt][0] * inv_lo, o[nt][1] * inv_lo);
        *(float2*)(out + (size_t)row_hi * EMBED + col) =
            make_float2(o[nt][2] * inv_hi, o[nt][3] * inv_hi);
    }
}

// ---------------------------------------------------------------------------
extern "C" void kernel_launch(void* const* d_in, const int* in_sizes, int n_in,
                              void* d_out, int out_size)
{
    const float* hidden = (const float*)d_in[0];   // (4096,1280)
    const float* cosv   = (const float*)d_in[1];   // (4096,80)
    const float* sinv   = (const float*)d_in[2];   // (4096,80)
    const float* w_qkv  = (const float*)d_in[3];   // (1280,3840)
    const float* b_qkv  = (const float*)d_in[4];   // (3840,)
    const float* w_proj = (const float*)d_in[5];   // (1280,1280)
    const float* b_proj = (const float*)d_in[6];   // (1280,)
    float* outp = (float*)d_out;                   // (4096,1280)

    float *qkv_ptr = nullptr, *attn_ptr = nullptr;
    cudaGetSymbolAddress((void**)&qkv_ptr, g_qkv);
    cudaGetSymbolAddress((void**)&attn_ptr, g_attn);

    cudaFuncSetAttribute(flash_tf32_kernel,
                         cudaFuncAttributeMaxDynamicSharedMemorySize,
                         FLASH_SMEM_BYTES);

    // 1) QKV projection (tf32 mma)
    dim3 g1(QKV_N / 128, SEQ / 128);
    gemm_tf32_kernel<<<g1, 256>>>(hidden, w_qkv, b_qkv, qkv_ptr,
                                  SEQ, QKV_N, EMBED);
    // 2) RoPE on Q,K
    int rope_total = SEQ * 1280;
    rope_kernel<<<(rope_total + 255) / 256, 256>>>(cosv, sinv, qkv_ptr);
    // 3) Flash attention (tf32 mma)
    flash_tf32_kernel<<<dim3(SEQ / 64, HEADS), 128, FLASH_SMEM_BYTES>>>(
        qkv_ptr, attn_ptr);
    // 4) Output projection (tf32 mma)
    dim3 g2(EMBED / 128, SEQ / 128);
    gemm_tf32_kernel<<<g2, 256>>>(attn_ptr, w_proj, b_proj, outp,
                                  SEQ, EMBED, EMBED);
}